// round 15
// baseline (speedup 1.0000x reference)
#include <cuda_runtime.h>
#include <cuda_fp16.h>
#include <math.h>
#include <stdint.h>

#define NN 100000
#define NE 1600000
#define NF 256
#define NH 128
#define NC 41
#define GS 48      // padded gs row (halfs)
#define HALF1 50048   // split point (multiple of 128 and 16)

#define SCAN_TILE 1024
#define NSB ((NN + SCAN_TILE - 1) / SCAN_TILE)

// ---------------- device scratch (static; no allocations allowed) ----------
__device__ float  g_deg[NN];        // sum of incoming edge weights (memset 0)
__device__ int    g_cnt[NN];        // incoming edge count        (memset 0)
__device__ int    g_rowptr[NN + 1];
__device__ int    g_cursor[NN];
__device__ int    g_bsum[NSB];
__device__ int    g_boff[NSB];
__device__ uint2  g_edge[NE];       // interleaved (src, weight-bits)
__device__ __half g_hsh[NN * NH];   // fp16: RAW x @ W1 (no dinv)
__device__ __half g_hrh[NN * NH];   // fp16: relu(layer1 out)
__device__ __half g_gsh[NN * GS];   // fp16: dinv * (hr @ W2), padded to 48

// dinv = rsqrt(1 + deg): self-loop weight 1 folded into the constant.
__device__ __forceinline__ float dinv_of(int i) {
    return rsqrtf(1.0f + g_deg[i]);
}

// ---------------- packed f32x2 helpers --------------------------------------
__device__ __forceinline__ unsigned long long pk2(float lo, float hi) {
    unsigned long long r;
    asm("mov.b64 %0, {%1, %2};" : "=l"(r) : "f"(lo), "f"(hi));
    return r;
}
__device__ __forceinline__ void upk2(unsigned long long v, float& lo, float& hi) {
    asm("mov.b64 {%0, %1}, %2;" : "=f"(lo), "=f"(hi) : "l"(v));
}
__device__ __forceinline__ void ffma2(unsigned long long& d,
                                      unsigned long long a,
                                      unsigned long long b) {
    asm("fma.rn.f32x2 %0, %1, %2, %0;" : "+l"(d) : "l"(a), "l"(b));
}
__device__ __forceinline__ void cp_async16(uint32_t saddr, const void* gptr) {
    asm volatile("cp.async.ca.shared.global [%0], [%1], 16;"
                 :: "r"(saddr), "l"(gptr) : "memory");
}
__device__ __forceinline__ void cp_async_commit() {
    asm volatile("cp.async.commit_group;" ::: "memory");
}
__device__ __forceinline__ void cp_async_wait0() {
    asm volatile("cp.async.wait_group 0;" ::: "memory");
}

// ---------------- histogram (deg starts at 0) -------------------------------
__global__ void k_hist(const int* __restrict__ ei, const float* __restrict__ ew) {
    int e = blockIdx.x * blockDim.x + threadIdx.x;
    if (e < NE) {
        int dst = ei[NE + e];
        atomicAdd(&g_deg[dst], ew[e]);
        atomicAdd(&g_cnt[dst], 1);
    }
}

// ---------------- 3-pass exclusive scan of g_cnt -> g_rowptr ---------------
__global__ void k_scan1() {
    __shared__ int sh[256];
    int b = blockIdx.x, t = threadIdx.x;
    int base = b * SCAN_TILE + t * 4;
    int s = 0;
#pragma unroll
    for (int j = 0; j < 4; j++) {
        int idx = base + j;
        if (idx < NN) s += g_cnt[idx];
    }
    sh[t] = s; __syncthreads();
    for (int off = 128; off > 0; off >>= 1) {
        if (t < off) sh[t] += sh[t + off];
        __syncthreads();
    }
    if (t == 0) g_bsum[b] = sh[0];
}

__global__ void k_scan2() {
    __shared__ int sh[NSB];
    int t = threadIdx.x;
    if (t < NSB) sh[t] = g_bsum[t];
    __syncthreads();
    if (t == 0) {
        int run = 0;
        for (int b = 0; b < NSB; b++) { int v = sh[b]; sh[b] = run; run += v; }
    }
    __syncthreads();
    if (t < NSB) g_boff[t] = sh[t];
}

__global__ void k_scan3() {
    __shared__ int sh[256];
    int b = blockIdx.x, t = threadIdx.x;
    int base = b * SCAN_TILE + t * 4;
    int v[4]; int s = 0;
#pragma unroll
    for (int j = 0; j < 4; j++) {
        int idx = base + j;
        v[j] = (idx < NN) ? g_cnt[idx] : 0;
        s += v[j];
    }
    sh[t] = s; __syncthreads();
    for (int off = 1; off < 256; off <<= 1) {
        int add = (t >= off) ? sh[t - off] : 0;
        __syncthreads();
        sh[t] += add;
        __syncthreads();
    }
    int excl = ((t > 0) ? sh[t - 1] : 0) + g_boff[b];
#pragma unroll
    for (int j = 0; j < 4; j++) {
        int idx = base + j;
        if (idx < NN) { g_rowptr[idx] = excl; g_cursor[idx] = excl; }
        excl += v[j];
    }
    if (b == 0 && t == 0) g_rowptr[NN] = NE;
}

__global__ void k_csr(const int* __restrict__ ei, const float* __restrict__ ew) {
    int e = blockIdx.x * blockDim.x + threadIdx.x;
    if (e < NE) {
        int src = ei[e];
        int dst = ei[NE + e];
        float w = ew[e];
        int pos = atomicAdd(&g_cursor[dst], 1);
        g_edge[pos] = make_uint2((uint32_t)src, __float_as_uint(w));
    }
}

// ---------------- packed-f32x2 GEMM: double-buffered, cp.async B ------------
// WHICH==0: A = x (fp32 ext), C = g_hsh RAW (no dinv) -- zero-dependency launch
// WHICH==1: A = g_hrh (fp16), C = g_gsh (dinv-scaled), rowbase for split runs
template<int BM, int BN, int BK, int TM, int TN, int K, int NOUT, int OSTR, int WHICH>
__global__ void __launch_bounds__((BM / TM) * (BN / TN), 2)
k_gemm_p(const float* __restrict__ Aext, const float* __restrict__ B, int rowbase) {
    const int NT   = (BM / TM) * (BN / TN);
    const int AST  = BM + 4;                 // A row stride (floats)
    const int APT  = BM * (BK / 4) / NT;     // float4 per thread (A fill)
    const int BCH  = BK * BN / 4 / NT;       // 16B chunks per thread (B, WHICH==0)
    const int BPTS = BK * BN / NT;           // floats per thread (B fill, WHICH==1)
    const int NTILES = K / BK;

    extern __shared__ float dsm[];
    float* Asm = dsm;                        // [2][BK][AST]
    float* Bsm = dsm + 2 * BK * AST;         // [2][BK][BN]

    __half* C = (WHICH == 0) ? g_hsh : g_gsh;

    int tid  = threadIdx.x;
    int row0 = rowbase + blockIdx.x * BM;
    int trow = tid / (BN / TN);
    int tcol = tid % (BN / TN);

    unsigned long long acc[TM / 2][TN];
#pragma unroll
    for (int i = 0; i < TM / 2; i++)
#pragma unroll
        for (int j = 0; j < TN; j++) acc[i][j] = 0ull;

    float4 apre[APT];
    float  bpres[(WHICH == 1) ? BPTS : 1];

    auto load_a = [&](int kt) {
#pragma unroll
        for (int u = 0; u < APT; u++) {
            int i = tid + u * NT;
            int m = i / (BK / 4), kq = i % (BK / 4);
            int gm = row0 + m;
            apre[u] = make_float4(0.f, 0.f, 0.f, 0.f);
            if (gm < NN) {
                if (WHICH == 0) {
                    apre[u] = *reinterpret_cast<const float4*>(
                        &Aext[(size_t)gm * K + kt + 4 * kq]);
                } else {
                    uint2 raw = *reinterpret_cast<const uint2*>(
                        &g_hrh[(size_t)gm * K + kt + 4 * kq]);
                    float2 a = __half22float2(*reinterpret_cast<__half2*>(&raw.x));
                    float2 b = __half22float2(*reinterpret_cast<__half2*>(&raw.y));
                    apre[u] = make_float4(a.x, a.y, b.x, b.y);
                }
            }
        }
    };
    auto store_a = [&](int buf) {
#pragma unroll
        for (int u = 0; u < APT; u++) {
            int i = tid + u * NT;
            int m = i / (BK / 4), kq = i % (BK / 4);
            Asm[(buf * BK + 4 * kq + 0) * AST + m] = apre[u].x;
            Asm[(buf * BK + 4 * kq + 1) * AST + m] = apre[u].y;
            Asm[(buf * BK + 4 * kq + 2) * AST + m] = apre[u].z;
            Asm[(buf * BK + 4 * kq + 3) * AST + m] = apre[u].w;
        }
    };
    auto issue_b = [&](int kt, int buf) {
        uint32_t sbase = (uint32_t)__cvta_generic_to_shared(Bsm);
#pragma unroll
        for (int u = 0; u < BCH; u++) {
            int i = tid + u * NT;
            int k = i / (BN / 4), nq = i % (BN / 4);
            cp_async16(sbase + ((buf * BK + k) * BN + 4 * nq) * 4,
                       &B[(size_t)(kt + k) * NOUT + 4 * nq]);
        }
        cp_async_commit();
    };
    auto load_b_s = [&](int kt) {
#pragma unroll
        for (int u = 0; u < BPTS; u++) {
            int i = tid + u * NT;
            int k = i / BN, n = i % BN;
            bpres[u] = (n < NOUT) ? B[(size_t)(kt + k) * NOUT + n] : 0.0f;
        }
    };
    auto store_b_s = [&](int buf) {
#pragma unroll
        for (int u = 0; u < BPTS; u++) {
            int i = tid + u * NT;
            int k = i / BN, n = i % BN;
            Bsm[(buf * BK + k) * BN + n] = bpres[u];
        }
    };

    load_a(0);
    if (WHICH == 0) issue_b(0, 0); else load_b_s(0);
    store_a(0);
    if (WHICH == 1) store_b_s(0);
    if (WHICH == 0) cp_async_wait0();
    __syncthreads();

#pragma unroll 1
    for (int t = 0; t < NTILES; t++) {
        if (t + 1 < NTILES) {
            load_a((t + 1) * BK);
            if (WHICH == 0) issue_b((t + 1) * BK, (t + 1) & 1);
            else            load_b_s((t + 1) * BK);
        }
        int buf = t & 1;
#pragma unroll
        for (int kk = 0; kk < BK; kk++) {
            unsigned long long ra[TM / 2];
            const ulonglong2* ap2 = reinterpret_cast<const ulonglong2*>(
                &Asm[(buf * BK + kk) * AST + trow * TM]);
#pragma unroll
            for (int i = 0; i < TM / 4; i++) {
                ulonglong2 q = ap2[i];
                ra[2 * i]     = q.x;
                ra[2 * i + 1] = q.y;
            }
            float4 bv = *reinterpret_cast<const float4*>(
                &Bsm[(buf * BK + kk) * BN + tcol * TN]);
            unsigned long long rb[TN];
            rb[0] = pk2(bv.x, bv.x);
            rb[1] = pk2(bv.y, bv.y);
            rb[2] = pk2(bv.z, bv.z);
            rb[3] = pk2(bv.w, bv.w);
#pragma unroll
            for (int i = 0; i < TM / 2; i++)
#pragma unroll
                for (int j = 0; j < TN; j++)
                    ffma2(acc[i][j], ra[i], rb[j]);
        }
        if (t + 1 < NTILES) {
            store_a((t + 1) & 1);
            if (WHICH == 1) store_b_s((t + 1) & 1);
            if (WHICH == 0) cp_async_wait0();
        }
        __syncthreads();
    }

    // epilogue: WHICH==0 stores raw; WHICH==1 scales by dinv. fp16, 8B stores.
    int nb = tcol * TN;
    bool nok = (nb < OSTR);
#pragma unroll
    for (int i = 0; i < TM / 2; i++) {
        int m0 = row0 + trow * TM + 2 * i;
        int m1 = m0 + 1;
        float r0[TN], r1[TN];
#pragma unroll
        for (int j = 0; j < TN; j++) upk2(acc[i][j], r0[j], r1[j]);
        if (nok && m0 < NN) {
            float dv = (WHICH == 0) ? 1.0f : dinv_of(m0);
            __half2 h0 = __floats2half2_rn(dv * r0[0], dv * r0[1]);
            __half2 h1 = __floats2half2_rn(dv * r0[2], dv * r0[3]);
            uint2 pkd = make_uint2(*reinterpret_cast<uint32_t*>(&h0),
                                   *reinterpret_cast<uint32_t*>(&h1));
            *reinterpret_cast<uint2*>(&C[(size_t)m0 * OSTR + nb]) = pkd;
        }
        if (nok && m1 < NN) {
            float dv = (WHICH == 0) ? 1.0f : dinv_of(m1);
            __half2 h0 = __floats2half2_rn(dv * r1[0], dv * r1[1]);
            __half2 h1 = __floats2half2_rn(dv * r1[2], dv * r1[3]);
            uint2 pkd = make_uint2(*reinterpret_cast<uint32_t*>(&h0),
                                   *reinterpret_cast<uint32_t*>(&h1));
            *reinterpret_cast<uint2*>(&C[(size_t)m1 * OSTR + nb]) = pkd;
        }
    }
}

// ---------------- pull layer 1: 16 lanes/node, dinv[src] folded into w ------
// hsh is RAW xW1; out[i] = relu(dv*acc + dv^2*self + b),
// acc = sum_e (w_e * dinv[src_e]) * hsh[src_e].
__global__ void k_pull1(const float* __restrict__ b1, int gbase, int glimit) {
    int g  = gbase + ((blockIdx.x * blockDim.x + threadIdx.x) >> 4);
    int hl = threadIdx.x & 15;
    if (g >= glimit) return;
    unsigned mask = 0xFFFFu << (threadIdx.x & 16);

    int rs = g_rowptr[g], re = g_rowptr[g + 1];
    unsigned long long acc2[4] = {0ull, 0ull, 0ull, 0ull};

    for (int base = rs; base < re; base += 16) {
        int cnt = re - base; if (cnt > 16) cnt = 16;
        int s = 0; float wv = 0.0f;
        if (hl < cnt) {
            uint2 e = g_edge[base + hl];
            s = (int)e.x;
            wv = __uint_as_float(e.y) * dinv_of(s);   // fold dinv[src], lane-parallel
        }
        for (int j = 0; j < cnt; j++) {
            int   sj = __shfl_sync(mask, s,  j, 16);
            float wj = __shfl_sync(mask, wv, j, 16);
            uint4 p = *reinterpret_cast<const uint4*>(&g_hsh[(size_t)sj * NH + hl * 8]);
            unsigned long long w2 = pk2(wj, wj);
            float2 f0 = __half22float2(*reinterpret_cast<__half2*>(&p.x));
            float2 f1 = __half22float2(*reinterpret_cast<__half2*>(&p.y));
            float2 f2 = __half22float2(*reinterpret_cast<__half2*>(&p.z));
            float2 f3 = __half22float2(*reinterpret_cast<__half2*>(&p.w));
            ffma2(acc2[0], pk2(f0.x, f0.y), w2);
            ffma2(acc2[1], pk2(f1.x, f1.y), w2);
            ffma2(acc2[2], pk2(f2.x, f2.y), w2);
            ffma2(acc2[3], pk2(f3.x, f3.y), w2);
        }
    }

    float acc[8];
    upk2(acc2[0], acc[0], acc[1]);
    upk2(acc2[1], acc[2], acc[3]);
    upk2(acc2[2], acc[4], acc[5]);
    upk2(acc2[3], acc[6], acc[7]);

    float dv  = dinv_of(g);
    float dv2 = dv * dv;
    uint4 sp = *reinterpret_cast<const uint4*>(&g_hsh[(size_t)g * NH + hl * 8]);
    float2 s0 = __half22float2(*reinterpret_cast<__half2*>(&sp.x));
    float2 s1 = __half22float2(*reinterpret_cast<__half2*>(&sp.y));
    float2 s2 = __half22float2(*reinterpret_cast<__half2*>(&sp.z));
    float2 s3 = __half22float2(*reinterpret_cast<__half2*>(&sp.w));
    float4 ba = *reinterpret_cast<const float4*>(&b1[hl * 8]);
    float4 bb = *reinterpret_cast<const float4*>(&b1[hl * 8 + 4]);
    float r[8];
    r[0] = fmaxf(dv * acc[0] + dv2 * s0.x + ba.x, 0.0f);
    r[1] = fmaxf(dv * acc[1] + dv2 * s0.y + ba.y, 0.0f);
    r[2] = fmaxf(dv * acc[2] + dv2 * s1.x + ba.z, 0.0f);
    r[3] = fmaxf(dv * acc[3] + dv2 * s1.y + ba.w, 0.0f);
    r[4] = fmaxf(dv * acc[4] + dv2 * s2.x + bb.x, 0.0f);
    r[5] = fmaxf(dv * acc[5] + dv2 * s2.y + bb.y, 0.0f);
    r[6] = fmaxf(dv * acc[6] + dv2 * s3.x + bb.z, 0.0f);
    r[7] = fmaxf(dv * acc[7] + dv2 * s3.y + bb.w, 0.0f);
    __half2 h0 = __floats2half2_rn(r[0], r[1]);
    __half2 h1 = __floats2half2_rn(r[2], r[3]);
    __half2 h2 = __floats2half2_rn(r[4], r[5]);
    __half2 h3 = __floats2half2_rn(r[6], r[7]);
    uint4 o;
    o.x = *reinterpret_cast<uint32_t*>(&h0);
    o.y = *reinterpret_cast<uint32_t*>(&h1);
    o.z = *reinterpret_cast<uint32_t*>(&h2);
    o.w = *reinterpret_cast<uint32_t*>(&h3);
    *reinterpret_cast<uint4*>(&g_hrh[(size_t)g * NH + hl * 8]) = o;
}

// ---------------- pull layer 2 + bias + log_softmax (fp16 gather) ----------
__global__ void k_pull2(const float* __restrict__ b2, float* __restrict__ out) {
    int gw   = (blockIdx.x * blockDim.x + threadIdx.x) >> 5;
    int lane = threadIdx.x & 31;
    if (gw >= NN) return;

    int rs = g_rowptr[gw], re = g_rowptr[gw + 1];
    bool act = (lane < GS / 2);
    float2 acc = make_float2(0.f, 0.f);

    for (int base = rs; base < re; base += 32) {
        int cnt = re - base; if (cnt > 32) cnt = 32;
        int s = 0; float wv = 0.0f;
        if (lane < cnt) {
            uint2 e = g_edge[base + lane];
            s = (int)e.x; wv = __uint_as_float(e.y);
        }
        for (int j = 0; j < cnt; j++) {
            int   sj = __shfl_sync(0xffffffffu, s,  j);
            float wj = __shfl_sync(0xffffffffu, wv, j);
            if (act) {
                uint32_t p = *reinterpret_cast<const uint32_t*>(
                    &g_gsh[(size_t)sj * GS + 2 * lane]);
                float2 f = __half22float2(*reinterpret_cast<__half2*>(&p));
                acc.x += wj * f.x; acc.y += wj * f.y;
            }
        }
    }

    float dv = dinv_of(gw);
    int f0 = 2 * lane, f1 = 2 * lane + 1;
    float v0 = -1e30f, v1 = -1e30f;
    if (act) {
        uint32_t sp = *reinterpret_cast<const uint32_t*>(
            &g_gsh[(size_t)gw * GS + 2 * lane]);
        float2 sf = __half22float2(*reinterpret_cast<__half2*>(&sp));
        if (f0 < NC) v0 = dv * (acc.x + sf.x) + b2[f0];
        if (f1 < NC) v1 = dv * (acc.y + sf.y) + b2[f1];
    }

    float m = fmaxf(v0, v1);
#pragma unroll
    for (int off = 16; off > 0; off >>= 1)
        m = fmaxf(m, __shfl_xor_sync(0xffffffffu, m, off));

    float s = ((f0 < NC && act) ? expf(v0 - m) : 0.0f)
            + ((f1 < NC && act) ? expf(v1 - m) : 0.0f);
#pragma unroll
    for (int off = 16; off > 0; off >>= 1)
        s += __shfl_xor_sync(0xffffffffu, s, off);

    float lse = logf(s) + m;
    if (act && f0 < NC) out[(size_t)gw * NC + f0] = v0 - lse;
    if (act && f1 < NC) out[(size_t)gw * NC + f1] = v1 - lse;
}

// ---------------- launch ---------------------------------------------------
// GEMM1 has zero deps -> launches at t=0 on main; the ENTIRE preprocessing
// chain (memsets, hist, scans, csr) runs on the side stream underneath it.
// pull1/gemm2 split in halves: gemm2_A (side) overlaps pull1_B (main).
extern "C" void kernel_launch(void* const* d_in, const int* in_sizes, int n_in,
                              void* d_out, int out_size) {
    const float* x  = (const float*)d_in[0];
    const int*   ei = (const int*)  d_in[1];
    const float* ew = (const float*)d_in[2];
    const float* W1 = (const float*)d_in[3];
    const float* b1 = (const float*)d_in[4];
    const float* W2 = (const float*)d_in[5];
    const float* b2 = (const float*)d_in[6];
    float* out = (float*)d_out;

    const int SM1 = 66560;   // GEMM1: BK=32
    const int SM2 = 25088;   // GEMM2: BK=16

    static cudaStream_t s_side = nullptr;
    static cudaEvent_t  s_fork = nullptr, s_join = nullptr;
    static cudaEvent_t  s_evA = nullptr, s_join2 = nullptr;
    static void *p_deg = nullptr, *p_cnt = nullptr;
    if (s_side == nullptr) {
        cudaFuncSetAttribute(k_gemm_p<128, 128, 32, 16, 4, NF, NH, NH, 0>,
                             cudaFuncAttributeMaxDynamicSharedMemorySize, SM1);
        cudaStreamCreateWithFlags(&s_side, cudaStreamNonBlocking);
        cudaEventCreateWithFlags(&s_fork, cudaEventDisableTiming);
        cudaEventCreateWithFlags(&s_join, cudaEventDisableTiming);
        cudaEventCreateWithFlags(&s_evA, cudaEventDisableTiming);
        cudaEventCreateWithFlags(&s_join2, cudaEventDisableTiming);
        cudaGetSymbolAddress(&p_deg, g_deg);
        cudaGetSymbolAddress(&p_cnt, g_cnt);
    }

    // fork side stream at t=0
    cudaEventRecord(s_fork, 0);
    cudaStreamWaitEvent(s_side, s_fork, 0);

    // side: full preprocessing chain
    cudaMemsetAsync(p_deg, 0, NN * sizeof(float), s_side);
    cudaMemsetAsync(p_cnt, 0, NN * sizeof(int), s_side);
    k_hist<<<(NE + 255) / 256, 256, 0, s_side>>>(ei, ew);
    k_scan1<<<NSB, 256, 0, s_side>>>();
    k_scan2<<<1, 128, 0, s_side>>>();
    k_scan3<<<NSB, 256, 0, s_side>>>();
    k_csr<<<(NE + 255) / 256, 256, 0, s_side>>>(ei, ew);
    cudaEventRecord(s_join, s_side);

    // main: GEMM1 (zero dependencies, raw hsh)
    k_gemm_p<128, 128, 32, 16, 4, NF, NH, NH, 0>
        <<<(NN + 127) / 128, 256, SM1>>>(x, W1, 0);

    // join CSR+deg, then split pull1
    cudaStreamWaitEvent(0, s_join, 0);
    k_pull1<<<(HALF1 * 16) / 256, 256>>>(b1, 0, HALF1);
    cudaEventRecord(s_evA, 0);
    k_pull1<<<((NN - HALF1) * 16 + 255) / 256, 256>>>(b1, HALF1, NN);

    // gemm2_A on side stream overlaps pull1_B
    cudaStreamWaitEvent(s_side, s_evA, 0);
    k_gemm_p<128, 64, 16, 16, 4, NH, NC, GS, 1>
        <<<HALF1 / 128, 128, SM2, s_side>>>(nullptr, W2, 0);
    cudaEventRecord(s_join2, s_side);

    // gemm2_B on main (after pull1_B)
    k_gemm_p<128, 64, 16, 16, 4, NH, NC, GS, 1>
        <<<(NN - HALF1 + 127) / 128, 128, SM2>>>(nullptr, W2, HALF1);

    // pull2 needs all of gs
    cudaStreamWaitEvent(0, s_join2, 0);
    k_pull2<<<(NN * 32 + 255) / 256, 256>>>(b2, out);
}

// round 16
// speedup vs baseline: 1.0263x; 1.0263x over previous
#include <cuda_runtime.h>
#include <cuda_fp16.h>
#include <math.h>
#include <stdint.h>

#define NN 100000
#define NE 1600000
#define NF 256
#define NH 128
#define NC 41
#define GS 48        // padded gs row (halfs)
#define HALF1 50048  // split point (multiple of 128 and 16)

#define SCAN_TILE 1024
#define NSB ((NN + SCAN_TILE - 1) / SCAN_TILE)

// ---------------- device scratch (static; no allocations allowed) ----------
__device__ float  g_deg[NN];        // sum of incoming edge weights (memset 0)
__device__ int    g_cnt[NN];        // incoming edge count        (memset 0)
__device__ int    g_rowptr[NN + 1];
__device__ int    g_cursor[NN];
__device__ int    g_bsum[NSB];
__device__ int    g_boff[NSB];
__device__ uint2  g_edge[NE];       // interleaved (src, weight-bits)
__device__ __half g_hsh[NN * NH];   // fp16: dinv * (x @ W1)
__device__ __half g_hrh[NN * NH];   // fp16: relu(layer1 out)
__device__ __half g_gsh[NN * GS];   // fp16: dinv * (hr @ W2), padded to 48

// dinv = rsqrt(1 + deg): self-loop weight 1 folded into the constant.
__device__ __forceinline__ float dinv_of(int i) {
    return rsqrtf(1.0f + g_deg[i]);
}

// ---------------- packed f32x2 helpers --------------------------------------
__device__ __forceinline__ unsigned long long pk2(float lo, float hi) {
    unsigned long long r;
    asm("mov.b64 %0, {%1, %2};" : "=l"(r) : "f"(lo), "f"(hi));
    return r;
}
__device__ __forceinline__ void upk2(unsigned long long v, float& lo, float& hi) {
    asm("mov.b64 {%0, %1}, %2;" : "=f"(lo), "=f"(hi) : "l"(v));
}
__device__ __forceinline__ void ffma2(unsigned long long& d,
                                      unsigned long long a,
                                      unsigned long long b) {
    asm("fma.rn.f32x2 %0, %1, %2, %0;" : "+l"(d) : "l"(a), "l"(b));
}
__device__ __forceinline__ void cp_async16(uint32_t saddr, const void* gptr) {
    asm volatile("cp.async.ca.shared.global [%0], [%1], 16;"
                 :: "r"(saddr), "l"(gptr) : "memory");
}
__device__ __forceinline__ void cp_async_commit() {
    asm volatile("cp.async.commit_group;" ::: "memory");
}
__device__ __forceinline__ void cp_async_wait0() {
    asm volatile("cp.async.wait_group 0;" ::: "memory");
}

// ---------------- histogram (deg starts at 0; self-loop folded in rsqrt) ---
__global__ void k_hist(const int* __restrict__ ei, const float* __restrict__ ew) {
    int e = blockIdx.x * blockDim.x + threadIdx.x;
    if (e < NE) {
        int dst = ei[NE + e];
        atomicAdd(&g_deg[dst], ew[e]);
        atomicAdd(&g_cnt[dst], 1);
    }
}

// ---------------- 3-pass exclusive scan of g_cnt -> g_rowptr ---------------
__global__ void k_scan1() {
    __shared__ int sh[256];
    int b = blockIdx.x, t = threadIdx.x;
    int base = b * SCAN_TILE + t * 4;
    int s = 0;
#pragma unroll
    for (int j = 0; j < 4; j++) {
        int idx = base + j;
        if (idx < NN) s += g_cnt[idx];
    }
    sh[t] = s; __syncthreads();
    for (int off = 128; off > 0; off >>= 1) {
        if (t < off) sh[t] += sh[t + off];
        __syncthreads();
    }
    if (t == 0) g_bsum[b] = sh[0];
}

__global__ void k_scan2() {
    __shared__ int sh[NSB];
    int t = threadIdx.x;
    if (t < NSB) sh[t] = g_bsum[t];
    __syncthreads();
    if (t == 0) {
        int run = 0;
        for (int b = 0; b < NSB; b++) { int v = sh[b]; sh[b] = run; run += v; }
    }
    __syncthreads();
    if (t < NSB) g_boff[t] = sh[t];
}

__global__ void k_scan3() {
    __shared__ int sh[256];
    int b = blockIdx.x, t = threadIdx.x;
    int base = b * SCAN_TILE + t * 4;
    int v[4]; int s = 0;
#pragma unroll
    for (int j = 0; j < 4; j++) {
        int idx = base + j;
        v[j] = (idx < NN) ? g_cnt[idx] : 0;
        s += v[j];
    }
    sh[t] = s; __syncthreads();
    for (int off = 1; off < 256; off <<= 1) {
        int add = (t >= off) ? sh[t - off] : 0;
        __syncthreads();
        sh[t] += add;
        __syncthreads();
    }
    int excl = ((t > 0) ? sh[t - 1] : 0) + g_boff[b];
#pragma unroll
    for (int j = 0; j < 4; j++) {
        int idx = base + j;
        if (idx < NN) { g_rowptr[idx] = excl; g_cursor[idx] = excl; }
        excl += v[j];
    }
    if (b == 0 && t == 0) g_rowptr[NN] = NE;
}

__global__ void k_csr(const int* __restrict__ ei, const float* __restrict__ ew) {
    int e = blockIdx.x * blockDim.x + threadIdx.x;
    if (e < NE) {
        int src = ei[e];
        int dst = ei[NE + e];
        float w = ew[e];
        int pos = atomicAdd(&g_cursor[dst], 1);
        g_edge[pos] = make_uint2((uint32_t)src, __float_as_uint(w));
    }
}

// ---------------- packed-f32x2 GEMM: double-buffered, cp.async B ------------
// WHICH==0: A = x (fp32 ext), C = g_hsh (K=NF, NOUT=NH, OSTR=NH, BK=32)
// WHICH==1: A = g_hrh (fp16), C = g_gsh (K=NH, NOUT=NC, OSTR=GS, BK=16)
template<int BM, int BN, int BK, int TM, int TN, int K, int NOUT, int OSTR, int WHICH>
__global__ void __launch_bounds__((BM / TM) * (BN / TN), 2)
k_gemm_p(const float* __restrict__ Aext, const float* __restrict__ B, int rowbase) {
    const int NT   = (BM / TM) * (BN / TN);
    const int AST  = BM + 4;                 // A row stride (floats)
    const int APT  = BM * (BK / 4) / NT;     // float4 per thread (A fill)
    const int BCH  = BK * BN / 4 / NT;       // 16B chunks per thread (B, WHICH==0)
    const int BPTS = BK * BN / NT;           // floats per thread (B fill, WHICH==1)
    const int NTILES = K / BK;

    extern __shared__ float dsm[];
    float* Asm = dsm;                        // [2][BK][AST]
    float* Bsm = dsm + 2 * BK * AST;         // [2][BK][BN]

    __half* C = (WHICH == 0) ? g_hsh : g_gsh;

    int tid  = threadIdx.x;
    int row0 = rowbase + blockIdx.x * BM;
    int trow = tid / (BN / TN);
    int tcol = tid % (BN / TN);

    unsigned long long acc[TM / 2][TN];
#pragma unroll
    for (int i = 0; i < TM / 2; i++)
#pragma unroll
        for (int j = 0; j < TN; j++) acc[i][j] = 0ull;

    float4 apre[APT];
    float  bpres[(WHICH == 1) ? BPTS : 1];

    auto load_a = [&](int kt) {
#pragma unroll
        for (int u = 0; u < APT; u++) {
            int i = tid + u * NT;
            int m = i / (BK / 4), kq = i % (BK / 4);
            int gm = row0 + m;
            apre[u] = make_float4(0.f, 0.f, 0.f, 0.f);
            if (gm < NN) {
                if (WHICH == 0) {
                    apre[u] = *reinterpret_cast<const float4*>(
                        &Aext[(size_t)gm * K + kt + 4 * kq]);
                } else {
                    uint2 raw = *reinterpret_cast<const uint2*>(
                        &g_hrh[(size_t)gm * K + kt + 4 * kq]);
                    float2 a = __half22float2(*reinterpret_cast<__half2*>(&raw.x));
                    float2 b = __half22float2(*reinterpret_cast<__half2*>(&raw.y));
                    apre[u] = make_float4(a.x, a.y, b.x, b.y);
                }
            }
        }
    };
    auto store_a = [&](int buf) {
#pragma unroll
        for (int u = 0; u < APT; u++) {
            int i = tid + u * NT;
            int m = i / (BK / 4), kq = i % (BK / 4);
            Asm[(buf * BK + 4 * kq + 0) * AST + m] = apre[u].x;
            Asm[(buf * BK + 4 * kq + 1) * AST + m] = apre[u].y;
            Asm[(buf * BK + 4 * kq + 2) * AST + m] = apre[u].z;
            Asm[(buf * BK + 4 * kq + 3) * AST + m] = apre[u].w;
        }
    };
    auto issue_b = [&](int kt, int buf) {
        uint32_t sbase = (uint32_t)__cvta_generic_to_shared(Bsm);
#pragma unroll
        for (int u = 0; u < BCH; u++) {
            int i = tid + u * NT;
            int k = i / (BN / 4), nq = i % (BN / 4);
            cp_async16(sbase + ((buf * BK + k) * BN + 4 * nq) * 4,
                       &B[(size_t)(kt + k) * NOUT + 4 * nq]);
        }
        cp_async_commit();
    };
    auto load_b_s = [&](int kt) {
#pragma unroll
        for (int u = 0; u < BPTS; u++) {
            int i = tid + u * NT;
            int k = i / BN, n = i % BN;
            bpres[u] = (n < NOUT) ? B[(size_t)(kt + k) * NOUT + n] : 0.0f;
        }
    };
    auto store_b_s = [&](int buf) {
#pragma unroll
        for (int u = 0; u < BPTS; u++) {
            int i = tid + u * NT;
            int k = i / BN, n = i % BN;
            Bsm[(buf * BK + k) * BN + n] = bpres[u];
        }
    };

    load_a(0);
    if (WHICH == 0) issue_b(0, 0); else load_b_s(0);
    store_a(0);
    if (WHICH == 1) store_b_s(0);
    if (WHICH == 0) cp_async_wait0();
    __syncthreads();

#pragma unroll 1
    for (int t = 0; t < NTILES; t++) {
        if (t + 1 < NTILES) {
            load_a((t + 1) * BK);
            if (WHICH == 0) issue_b((t + 1) * BK, (t + 1) & 1);
            else            load_b_s((t + 1) * BK);
        }
        int buf = t & 1;
#pragma unroll
        for (int kk = 0; kk < BK; kk++) {
            unsigned long long ra[TM / 2];
            const ulonglong2* ap2 = reinterpret_cast<const ulonglong2*>(
                &Asm[(buf * BK + kk) * AST + trow * TM]);
#pragma unroll
            for (int i = 0; i < TM / 4; i++) {
                ulonglong2 q = ap2[i];
                ra[2 * i]     = q.x;
                ra[2 * i + 1] = q.y;
            }
            float4 bv = *reinterpret_cast<const float4*>(
                &Bsm[(buf * BK + kk) * BN + tcol * TN]);
            unsigned long long rb[TN];
            rb[0] = pk2(bv.x, bv.x);
            rb[1] = pk2(bv.y, bv.y);
            rb[2] = pk2(bv.z, bv.z);
            rb[3] = pk2(bv.w, bv.w);
#pragma unroll
            for (int i = 0; i < TM / 2; i++)
#pragma unroll
                for (int j = 0; j < TN; j++)
                    ffma2(acc[i][j], ra[i], rb[j]);
        }
        if (t + 1 < NTILES) {
            store_a((t + 1) & 1);
            if (WHICH == 1) store_b_s((t + 1) & 1);
            if (WHICH == 0) cp_async_wait0();
        }
        __syncthreads();
    }

    // epilogue: dinv = rsqrt(1 + deg) inline, convert to fp16, 8B stores
    int nb = tcol * TN;
    bool nok = (nb < OSTR);   // for WHICH==1, skip n in [48,64)
#pragma unroll
    for (int i = 0; i < TM / 2; i++) {
        int m0 = row0 + trow * TM + 2 * i;
        int m1 = m0 + 1;
        float r0[TN], r1[TN];
#pragma unroll
        for (int j = 0; j < TN; j++) upk2(acc[i][j], r0[j], r1[j]);
        if (nok && m0 < NN) {
            float dv = dinv_of(m0);
            __half2 h0 = __floats2half2_rn(dv * r0[0], dv * r0[1]);
            __half2 h1 = __floats2half2_rn(dv * r0[2], dv * r0[3]);
            uint2 pkd = make_uint2(*reinterpret_cast<uint32_t*>(&h0),
                                   *reinterpret_cast<uint32_t*>(&h1));
            *reinterpret_cast<uint2*>(&C[(size_t)m0 * OSTR + nb]) = pkd;
        }
        if (nok && m1 < NN) {
            float dv = dinv_of(m1);
            __half2 h0 = __floats2half2_rn(dv * r1[0], dv * r1[1]);
            __half2 h1 = __floats2half2_rn(dv * r1[2], dv * r1[3]);
            uint2 pkd = make_uint2(*reinterpret_cast<uint32_t*>(&h0),
                                   *reinterpret_cast<uint32_t*>(&h1));
            *reinterpret_cast<uint2*>(&C[(size_t)m1 * OSTR + nb]) = pkd;
        }
    }
}

// ---------------- pull layer 1: 16 lanes/node, LDG.128, FFMA2 accumulate ---
__global__ void k_pull1(const float* __restrict__ b1, int gbase, int glimit) {
    int g  = gbase + ((blockIdx.x * blockDim.x + threadIdx.x) >> 4);
    int hl = threadIdx.x & 15;
    if (g >= glimit) return;
    unsigned mask = 0xFFFFu << (threadIdx.x & 16);

    int rs = g_rowptr[g], re = g_rowptr[g + 1];
    unsigned long long acc2[4] = {0ull, 0ull, 0ull, 0ull};

    for (int base = rs; base < re; base += 16) {
        int cnt = re - base; if (cnt > 16) cnt = 16;
        int s = 0; float wv = 0.0f;
        if (hl < cnt) {
            uint2 e = g_edge[base + hl];
            s = (int)e.x; wv = __uint_as_float(e.y);
        }
        for (int j = 0; j < cnt; j++) {
            int   sj = __shfl_sync(mask, s,  j, 16);
            float wj = __shfl_sync(mask, wv, j, 16);
            uint4 p = *reinterpret_cast<const uint4*>(&g_hsh[(size_t)sj * NH + hl * 8]);
            unsigned long long w2 = pk2(wj, wj);
            float2 f0 = __half22float2(*reinterpret_cast<__half2*>(&p.x));
            float2 f1 = __half22float2(*reinterpret_cast<__half2*>(&p.y));
            float2 f2 = __half22float2(*reinterpret_cast<__half2*>(&p.z));
            float2 f3 = __half22float2(*reinterpret_cast<__half2*>(&p.w));
            ffma2(acc2[0], pk2(f0.x, f0.y), w2);
            ffma2(acc2[1], pk2(f1.x, f1.y), w2);
            ffma2(acc2[2], pk2(f2.x, f2.y), w2);
            ffma2(acc2[3], pk2(f3.x, f3.y), w2);
        }
    }

    float acc[8];
    upk2(acc2[0], acc[0], acc[1]);
    upk2(acc2[1], acc[2], acc[3]);
    upk2(acc2[2], acc[4], acc[5]);
    upk2(acc2[3], acc[6], acc[7]);

    float dv = dinv_of(g);
    uint4 sp = *reinterpret_cast<const uint4*>(&g_hsh[(size_t)g * NH + hl * 8]);
    float2 s0 = __half22float2(*reinterpret_cast<__half2*>(&sp.x));
    float2 s1 = __half22float2(*reinterpret_cast<__half2*>(&sp.y));
    float2 s2 = __half22float2(*reinterpret_cast<__half2*>(&sp.z));
    float2 s3 = __half22float2(*reinterpret_cast<__half2*>(&sp.w));
    float4 ba = *reinterpret_cast<const float4*>(&b1[hl * 8]);
    float4 bb = *reinterpret_cast<const float4*>(&b1[hl * 8 + 4]);
    float r[8];
    r[0] = fmaxf(dv * (acc[0] + s0.x) + ba.x, 0.0f);
    r[1] = fmaxf(dv * (acc[1] + s0.y) + ba.y, 0.0f);
    r[2] = fmaxf(dv * (acc[2] + s1.x) + ba.z, 0.0f);
    r[3] = fmaxf(dv * (acc[3] + s1.y) + ba.w, 0.0f);
    r[4] = fmaxf(dv * (acc[4] + s2.x) + bb.x, 0.0f);
    r[5] = fmaxf(dv * (acc[5] + s2.y) + bb.y, 0.0f);
    r[6] = fmaxf(dv * (acc[6] + s3.x) + bb.z, 0.0f);
    r[7] = fmaxf(dv * (acc[7] + s3.y) + bb.w, 0.0f);
    __half2 h0 = __floats2half2_rn(r[0], r[1]);
    __half2 h1 = __floats2half2_rn(r[2], r[3]);
    __half2 h2 = __floats2half2_rn(r[4], r[5]);
    __half2 h3 = __floats2half2_rn(r[6], r[7]);
    uint4 o;
    o.x = *reinterpret_cast<uint32_t*>(&h0);
    o.y = *reinterpret_cast<uint32_t*>(&h1);
    o.z = *reinterpret_cast<uint32_t*>(&h2);
    o.w = *reinterpret_cast<uint32_t*>(&h3);
    *reinterpret_cast<uint4*>(&g_hrh[(size_t)g * NH + hl * 8]) = o;
}

// ---------------- pull layer 2 + bias + log_softmax (fp16 gather) ----------
__global__ void k_pull2(const float* __restrict__ b2, float* __restrict__ out) {
    int gw   = (blockIdx.x * blockDim.x + threadIdx.x) >> 5;
    int lane = threadIdx.x & 31;
    if (gw >= NN) return;

    int rs = g_rowptr[gw], re = g_rowptr[gw + 1];
    bool act = (lane < GS / 2);
    float2 acc = make_float2(0.f, 0.f);

    for (int base = rs; base < re; base += 32) {
        int cnt = re - base; if (cnt > 32) cnt = 32;
        int s = 0; float wv = 0.0f;
        if (lane < cnt) {
            uint2 e = g_edge[base + lane];
            s = (int)e.x; wv = __uint_as_float(e.y);
        }
        for (int j = 0; j < cnt; j++) {
            int   sj = __shfl_sync(0xffffffffu, s,  j);
            float wj = __shfl_sync(0xffffffffu, wv, j);
            if (act) {
                uint32_t p = *reinterpret_cast<const uint32_t*>(
                    &g_gsh[(size_t)sj * GS + 2 * lane]);
                float2 f = __half22float2(*reinterpret_cast<__half2*>(&p));
                acc.x += wj * f.x; acc.y += wj * f.y;
            }
        }
    }

    float dv = dinv_of(gw);
    int f0 = 2 * lane, f1 = 2 * lane + 1;
    float v0 = -1e30f, v1 = -1e30f;
    if (act) {
        uint32_t sp = *reinterpret_cast<const uint32_t*>(
            &g_gsh[(size_t)gw * GS + 2 * lane]);
        float2 sf = __half22float2(*reinterpret_cast<__half2*>(&sp));
        if (f0 < NC) v0 = dv * (acc.x + sf.x) + b2[f0];
        if (f1 < NC) v1 = dv * (acc.y + sf.y) + b2[f1];
    }

    float m = fmaxf(v0, v1);
#pragma unroll
    for (int off = 16; off > 0; off >>= 1)
        m = fmaxf(m, __shfl_xor_sync(0xffffffffu, m, off));

    float s = ((f0 < NC && act) ? expf(v0 - m) : 0.0f)
            + ((f1 < NC && act) ? expf(v1 - m) : 0.0f);
#pragma unroll
    for (int off = 16; off > 0; off >>= 1)
        s += __shfl_xor_sync(0xffffffffu, s, off);

    float lse = logf(s) + m;
    if (act && f0 < NC) out[(size_t)gw * NC + f0] = v0 - lse;
    if (act && f1 < NC) out[(size_t)gw * NC + f1] = v1 - lse;
}

// ---------------- launch ---------------------------------------------------
// R14 base schedule (measured best): memsets + hist serial on main; ONLY the
// light scan/csr chain forks to the side stream under GEMM1 (fits in its
// wave-3 holes). New this round: pull1/gemm2 half-split so gemm2_A (side)
// overlaps pull1_B (main).
extern "C" void kernel_launch(void* const* d_in, const int* in_sizes, int n_in,
                              void* d_out, int out_size) {
    const float* x  = (const float*)d_in[0];
    const int*   ei = (const int*)  d_in[1];
    const float* ew = (const float*)d_in[2];
    const float* W1 = (const float*)d_in[3];
    const float* b1 = (const float*)d_in[4];
    const float* W2 = (const float*)d_in[5];
    const float* b2 = (const float*)d_in[6];
    float* out = (float*)d_out;

    const int SM1 = 66560;   // GEMM1: BK=32
    const int SM2 = 25088;   // GEMM2: BK=16

    static cudaStream_t s_side = nullptr;
    static cudaEvent_t  s_fork = nullptr, s_join = nullptr;
    static cudaEvent_t  s_evA = nullptr, s_join2 = nullptr;
    static void *p_deg = nullptr, *p_cnt = nullptr;
    if (s_side == nullptr) {
        cudaFuncSetAttribute(k_gemm_p<128, 128, 32, 16, 4, NF, NH, NH, 0>,
                             cudaFuncAttributeMaxDynamicSharedMemorySize, SM1);
        cudaStreamCreateWithFlags(&s_side, cudaStreamNonBlocking);
        cudaEventCreateWithFlags(&s_fork, cudaEventDisableTiming);
        cudaEventCreateWithFlags(&s_join, cudaEventDisableTiming);
        cudaEventCreateWithFlags(&s_evA, cudaEventDisableTiming);
        cudaEventCreateWithFlags(&s_join2, cudaEventDisableTiming);
        cudaGetSymbolAddress(&p_deg, g_deg);
        cudaGetSymbolAddress(&p_cnt, g_cnt);
    }

    cudaMemsetAsync(p_deg, 0, NN * sizeof(float), 0);
    cudaMemsetAsync(p_cnt, 0, NN * sizeof(int), 0);
    k_hist<<<(NE + 255) / 256, 256>>>(ei, ew);

    // fork: side stream builds the CSR while main stream runs GEMM1
    cudaEventRecord(s_fork, 0);
    cudaStreamWaitEvent(s_side, s_fork, 0);
    k_scan1<<<NSB, 256, 0, s_side>>>();
    k_scan2<<<1, 128, 0, s_side>>>();
    k_scan3<<<NSB, 256, 0, s_side>>>();
    k_csr<<<(NE + 255) / 256, 256, 0, s_side>>>(ei, ew);
    cudaEventRecord(s_join, s_side);

    // layer 1 GEMM: hsh = fp16(dinv * (x @ W1))
    k_gemm_p<128, 128, 32, 16, 4, NF, NH, NH, 0>
        <<<(NN + 127) / 128, 256, SM1>>>(x, W1, 0);

    // join CSR, then split pull1: A half, then B half
    cudaStreamWaitEvent(0, s_join, 0);
    k_pull1<<<(HALF1 * 16) / 256, 256>>>(b1, 0, HALF1);
    cudaEventRecord(s_evA, 0);
    k_pull1<<<((NN - HALF1) * 16 + 255) / 256, 256>>>(b1, HALF1, NN);

    // gemm2_A on side stream overlaps pull1_B on main
    cudaStreamWaitEvent(s_side, s_evA, 0);
    k_gemm_p<128, 64, 16, 16, 4, NH, NC, GS, 1>
        <<<HALF1 / 128, 128, SM2, s_side>>>(nullptr, W2, 0);
    cudaEventRecord(s_join2, s_side);

    // gemm2_B on main (after pull1_B)
    k_gemm_p<128, 64, 16, 16, 4, NH, NC, GS, 1>
        <<<(NN - HALF1 + 127) / 128, 128, SM2>>>(nullptr, W2, HALF1);

    // pull2 needs all of gs
    cudaStreamWaitEvent(0, s_join2, 0);
    k_pull2<<<(NN * 32 + 255) / 256, 256>>>(b2, out);
}

// round 17
// speedup vs baseline: 1.0597x; 1.0326x over previous
#include <cuda_runtime.h>
#include <cuda_fp16.h>
#include <math.h>
#include <stdint.h>

#define NN 100000
#define NE 1600000
#define NF 256
#define NH 128
#define NC 41
#define GS 48   // padded gs row (halfs)

#define SCAN_TILE 1024
#define NSB ((NN + SCAN_TILE - 1) / SCAN_TILE)

// ---------------- device scratch (static; no allocations allowed) ----------
// Packed per-node histogram: bits [52:64) = incoming-edge count,
// bits [0:52) = sum of edge weights in 2^-32 fixed point. memset to 0.
__device__ unsigned long long g_pk[NN];
__device__ int    g_rowptr[NN + 1];
__device__ int    g_cursor[NN];
__device__ int    g_bsum[NSB];
__device__ int    g_boff[NSB];
__device__ uint2  g_edge[NE];       // interleaved (src, weight-bits)
__device__ __half g_hsh[NN * NH];   // fp16: dinv * (x @ W1)
__device__ __half g_hrh[NN * NH];   // fp16: relu(layer1 out)
__device__ __half g_gsh[NN * GS];   // fp16: dinv * (hr @ W2), padded to 48

#define PK_MASK 0xFFFFFFFFFFFFFull  // low 52 bits

__device__ __forceinline__ int cnt_of(int i) {
    return (int)(g_pk[i] >> 52);
}
// dinv = rsqrt(1 + deg): self-loop weight 1 folded into the constant.
__device__ __forceinline__ float dinv_of(int i) {
    float deg = (float)(g_pk[i] & PK_MASK) * (1.0f / 4294967296.0f);
    return rsqrtf(1.0f + deg);
}

// ---------------- packed f32x2 helpers --------------------------------------
__device__ __forceinline__ unsigned long long pk2(float lo, float hi) {
    unsigned long long r;
    asm("mov.b64 %0, {%1, %2};" : "=l"(r) : "f"(lo), "f"(hi));
    return r;
}
__device__ __forceinline__ void upk2(unsigned long long v, float& lo, float& hi) {
    asm("mov.b64 {%0, %1}, %2;" : "=f"(lo), "=f"(hi) : "l"(v));
}
__device__ __forceinline__ void ffma2(unsigned long long& d,
                                      unsigned long long a,
                                      unsigned long long b) {
    asm("fma.rn.f32x2 %0, %1, %2, %0;" : "+l"(d) : "l"(a), "l"(b));
}
__device__ __forceinline__ void cp_async16(uint32_t saddr, const void* gptr) {
    asm volatile("cp.async.ca.shared.global [%0], [%1], 16;"
                 :: "r"(saddr), "l"(gptr) : "memory");
}
__device__ __forceinline__ void cp_async_commit() {
    asm volatile("cp.async.commit_group;" ::: "memory");
}
__device__ __forceinline__ void cp_async_wait0() {
    asm volatile("cp.async.wait_group 0;" ::: "memory");
}

// ---------------- histogram: ONE u64 atomic per edge ------------------------
__global__ void k_hist(const int* __restrict__ ei, const float* __restrict__ ew) {
    int e = blockIdx.x * blockDim.x + threadIdx.x;
    if (e < NE) {
        int dst = ei[NE + e];
        float w = ew[e];
        unsigned long long wf = (unsigned long long)(w * 4294967296.0f);
        atomicAdd(&g_pk[dst], (1ull << 52) | wf);
    }
}

// ---------------- 3-pass exclusive scan of cnt -> g_rowptr ------------------
__global__ void k_scan1() {
    __shared__ int sh[256];
    int b = blockIdx.x, t = threadIdx.x;
    int base = b * SCAN_TILE + t * 4;
    int s = 0;
#pragma unroll
    for (int j = 0; j < 4; j++) {
        int idx = base + j;
        if (idx < NN) s += cnt_of(idx);
    }
    sh[t] = s; __syncthreads();
    for (int off = 128; off > 0; off >>= 1) {
        if (t < off) sh[t] += sh[t + off];
        __syncthreads();
    }
    if (t == 0) g_bsum[b] = sh[0];
}

__global__ void k_scan2() {
    __shared__ int sh[NSB];
    int t = threadIdx.x;
    if (t < NSB) sh[t] = g_bsum[t];
    __syncthreads();
    if (t == 0) {
        int run = 0;
        for (int b = 0; b < NSB; b++) { int v = sh[b]; sh[b] = run; run += v; }
    }
    __syncthreads();
    if (t < NSB) g_boff[t] = sh[t];
}

__global__ void k_scan3() {
    __shared__ int sh[256];
    int b = blockIdx.x, t = threadIdx.x;
    int base = b * SCAN_TILE + t * 4;
    int v[4]; int s = 0;
#pragma unroll
    for (int j = 0; j < 4; j++) {
        int idx = base + j;
        v[j] = (idx < NN) ? cnt_of(idx) : 0;
        s += v[j];
    }
    sh[t] = s; __syncthreads();
    for (int off = 1; off < 256; off <<= 1) {
        int add = (t >= off) ? sh[t - off] : 0;
        __syncthreads();
        sh[t] += add;
        __syncthreads();
    }
    int excl = ((t > 0) ? sh[t - 1] : 0) + g_boff[b];
#pragma unroll
    for (int j = 0; j < 4; j++) {
        int idx = base + j;
        if (idx < NN) { g_rowptr[idx] = excl; g_cursor[idx] = excl; }
        excl += v[j];
    }
    if (b == 0 && t == 0) g_rowptr[NN] = NE;
}

__global__ void k_csr(const int* __restrict__ ei, const float* __restrict__ ew) {
    int e = blockIdx.x * blockDim.x + threadIdx.x;
    if (e < NE) {
        int src = ei[e];
        int dst = ei[NE + e];
        float w = ew[e];
        int pos = atomicAdd(&g_cursor[dst], 1);
        g_edge[pos] = make_uint2((uint32_t)src, __float_as_uint(w));
    }
}

// ---------------- packed-f32x2 GEMM: double-buffered, cp.async B ------------
// WHICH==0: A = x (fp32 ext), C = g_hsh (K=NF, NOUT=NH, OSTR=NH, BK=32)
// WHICH==1: A = g_hrh (fp16), C = g_gsh (K=NH, NOUT=NC, OSTR=GS, BK=16)
template<int BM, int BN, int BK, int TM, int TN, int K, int NOUT, int OSTR, int WHICH>
__global__ void __launch_bounds__((BM / TM) * (BN / TN), 2)
k_gemm_p(const float* __restrict__ Aext, const float* __restrict__ B) {
    const int NT   = (BM / TM) * (BN / TN);
    const int AST  = BM + 4;                 // A row stride (floats)
    const int APT  = BM * (BK / 4) / NT;     // float4 per thread (A fill)
    const int BCH  = BK * BN / 4 / NT;       // 16B chunks per thread (B, WHICH==0)
    const int BPTS = BK * BN / NT;           // floats per thread (B fill, WHICH==1)
    const int NTILES = K / BK;

    extern __shared__ float dsm[];
    float* Asm = dsm;                        // [2][BK][AST]
    float* Bsm = dsm + 2 * BK * AST;         // [2][BK][BN]

    __half* C = (WHICH == 0) ? g_hsh : g_gsh;

    int tid  = threadIdx.x;
    int row0 = blockIdx.x * BM;
    int trow = tid / (BN / TN);
    int tcol = tid % (BN / TN);

    unsigned long long acc[TM / 2][TN];
#pragma unroll
    for (int i = 0; i < TM / 2; i++)
#pragma unroll
        for (int j = 0; j < TN; j++) acc[i][j] = 0ull;

    float4 apre[APT];
    float  bpres[(WHICH == 1) ? BPTS : 1];

    auto load_a = [&](int kt) {
#pragma unroll
        for (int u = 0; u < APT; u++) {
            int i = tid + u * NT;
            int m = i / (BK / 4), kq = i % (BK / 4);
            int gm = row0 + m;
            apre[u] = make_float4(0.f, 0.f, 0.f, 0.f);
            if (gm < NN) {
                if (WHICH == 0) {
                    apre[u] = *reinterpret_cast<const float4*>(
                        &Aext[(size_t)gm * K + kt + 4 * kq]);
                } else {
                    uint2 raw = *reinterpret_cast<const uint2*>(
                        &g_hrh[(size_t)gm * K + kt + 4 * kq]);
                    float2 a = __half22float2(*reinterpret_cast<__half2*>(&raw.x));
                    float2 b = __half22float2(*reinterpret_cast<__half2*>(&raw.y));
                    apre[u] = make_float4(a.x, a.y, b.x, b.y);
                }
            }
        }
    };
    auto store_a = [&](int buf) {
#pragma unroll
        for (int u = 0; u < APT; u++) {
            int i = tid + u * NT;
            int m = i / (BK / 4), kq = i % (BK / 4);
            Asm[(buf * BK + 4 * kq + 0) * AST + m] = apre[u].x;
            Asm[(buf * BK + 4 * kq + 1) * AST + m] = apre[u].y;
            Asm[(buf * BK + 4 * kq + 2) * AST + m] = apre[u].z;
            Asm[(buf * BK + 4 * kq + 3) * AST + m] = apre[u].w;
        }
    };
    auto issue_b = [&](int kt, int buf) {
        uint32_t sbase = (uint32_t)__cvta_generic_to_shared(Bsm);
#pragma unroll
        for (int u = 0; u < BCH; u++) {
            int i = tid + u * NT;
            int k = i / (BN / 4), nq = i % (BN / 4);
            cp_async16(sbase + ((buf * BK + k) * BN + 4 * nq) * 4,
                       &B[(size_t)(kt + k) * NOUT + 4 * nq]);
        }
        cp_async_commit();
    };
    auto load_b_s = [&](int kt) {
#pragma unroll
        for (int u = 0; u < BPTS; u++) {
            int i = tid + u * NT;
            int k = i / BN, n = i % BN;
            bpres[u] = (n < NOUT) ? B[(size_t)(kt + k) * NOUT + n] : 0.0f;
        }
    };
    auto store_b_s = [&](int buf) {
#pragma unroll
        for (int u = 0; u < BPTS; u++) {
            int i = tid + u * NT;
            int k = i / BN, n = i % BN;
            Bsm[(buf * BK + k) * BN + n] = bpres[u];
        }
    };

    load_a(0);
    if (WHICH == 0) issue_b(0, 0); else load_b_s(0);
    store_a(0);
    if (WHICH == 1) store_b_s(0);
    if (WHICH == 0) cp_async_wait0();
    __syncthreads();

#pragma unroll 1
    for (int t = 0; t < NTILES; t++) {
        if (t + 1 < NTILES) {
            load_a((t + 1) * BK);
            if (WHICH == 0) issue_b((t + 1) * BK, (t + 1) & 1);
            else            load_b_s((t + 1) * BK);
        }
        int buf = t & 1;
#pragma unroll
        for (int kk = 0; kk < BK; kk++) {
            unsigned long long ra[TM / 2];
            const ulonglong2* ap2 = reinterpret_cast<const ulonglong2*>(
                &Asm[(buf * BK + kk) * AST + trow * TM]);
#pragma unroll
            for (int i = 0; i < TM / 4; i++) {
                ulonglong2 q = ap2[i];
                ra[2 * i]     = q.x;
                ra[2 * i + 1] = q.y;
            }
            float4 bv = *reinterpret_cast<const float4*>(
                &Bsm[(buf * BK + kk) * BN + tcol * TN]);
            unsigned long long rb[TN];
            rb[0] = pk2(bv.x, bv.x);
            rb[1] = pk2(bv.y, bv.y);
            rb[2] = pk2(bv.z, bv.z);
            rb[3] = pk2(bv.w, bv.w);
#pragma unroll
            for (int i = 0; i < TM / 2; i++)
#pragma unroll
                for (int j = 0; j < TN; j++)
                    ffma2(acc[i][j], ra[i], rb[j]);
        }
        if (t + 1 < NTILES) {
            store_a((t + 1) & 1);
            if (WHICH == 1) store_b_s((t + 1) & 1);
            if (WHICH == 0) cp_async_wait0();
        }
        __syncthreads();
    }

    // epilogue: dinv = rsqrt(1 + deg) inline, convert to fp16, 8B stores
    int nb = tcol * TN;
    bool nok = (nb < OSTR);   // for WHICH==1, skip n in [48,64)
#pragma unroll
    for (int i = 0; i < TM / 2; i++) {
        int m0 = row0 + trow * TM + 2 * i;
        int m1 = m0 + 1;
        float r0[TN], r1[TN];
#pragma unroll
        for (int j = 0; j < TN; j++) upk2(acc[i][j], r0[j], r1[j]);
        if (nok && m0 < NN) {
            float dv = dinv_of(m0);
            __half2 h0 = __floats2half2_rn(dv * r0[0], dv * r0[1]);
            __half2 h1 = __floats2half2_rn(dv * r0[2], dv * r0[3]);
            uint2 pkd = make_uint2(*reinterpret_cast<uint32_t*>(&h0),
                                   *reinterpret_cast<uint32_t*>(&h1));
            *reinterpret_cast<uint2*>(&C[(size_t)m0 * OSTR + nb]) = pkd;
        }
        if (nok && m1 < NN) {
            float dv = dinv_of(m1);
            __half2 h0 = __floats2half2_rn(dv * r1[0], dv * r1[1]);
            __half2 h1 = __floats2half2_rn(dv * r1[2], dv * r1[3]);
            uint2 pkd = make_uint2(*reinterpret_cast<uint32_t*>(&h0),
                                   *reinterpret_cast<uint32_t*>(&h1));
            *reinterpret_cast<uint2*>(&C[(size_t)m1 * OSTR + nb]) = pkd;
        }
    }
}

// ---------------- pull layer 1: 16 lanes/node, LDG.128, FFMA2 accumulate ---
__global__ void k_pull1(const float* __restrict__ b1) {
    int g  = (blockIdx.x * blockDim.x + threadIdx.x) >> 4;
    int hl = threadIdx.x & 15;
    if (g >= NN) return;
    unsigned mask = 0xFFFFu << (threadIdx.x & 16);

    int rs = g_rowptr[g], re = g_rowptr[g + 1];
    unsigned long long acc2[4] = {0ull, 0ull, 0ull, 0ull};

    for (int base = rs; base < re; base += 16) {
        int cnt = re - base; if (cnt > 16) cnt = 16;
        int s = 0; float wv = 0.0f;
        if (hl < cnt) {
            uint2 e = g_edge[base + hl];
            s = (int)e.x; wv = __uint_as_float(e.y);
        }
        for (int j = 0; j < cnt; j++) {
            int   sj = __shfl_sync(mask, s,  j, 16);
            float wj = __shfl_sync(mask, wv, j, 16);
            uint4 p = *reinterpret_cast<const uint4*>(&g_hsh[(size_t)sj * NH + hl * 8]);
            unsigned long long w2 = pk2(wj, wj);
            float2 f0 = __half22float2(*reinterpret_cast<__half2*>(&p.x));
            float2 f1 = __half22float2(*reinterpret_cast<__half2*>(&p.y));
            float2 f2 = __half22float2(*reinterpret_cast<__half2*>(&p.z));
            float2 f3 = __half22float2(*reinterpret_cast<__half2*>(&p.w));
            ffma2(acc2[0], pk2(f0.x, f0.y), w2);
            ffma2(acc2[1], pk2(f1.x, f1.y), w2);
            ffma2(acc2[2], pk2(f2.x, f2.y), w2);
            ffma2(acc2[3], pk2(f3.x, f3.y), w2);
        }
    }

    float acc[8];
    upk2(acc2[0], acc[0], acc[1]);
    upk2(acc2[1], acc[2], acc[3]);
    upk2(acc2[2], acc[4], acc[5]);
    upk2(acc2[3], acc[6], acc[7]);

    float dv = dinv_of(g);
    uint4 sp = *reinterpret_cast<const uint4*>(&g_hsh[(size_t)g * NH + hl * 8]);
    float2 s0 = __half22float2(*reinterpret_cast<__half2*>(&sp.x));
    float2 s1 = __half22float2(*reinterpret_cast<__half2*>(&sp.y));
    float2 s2 = __half22float2(*reinterpret_cast<__half2*>(&sp.z));
    float2 s3 = __half22float2(*reinterpret_cast<__half2*>(&sp.w));
    float4 ba = *reinterpret_cast<const float4*>(&b1[hl * 8]);
    float4 bb = *reinterpret_cast<const float4*>(&b1[hl * 8 + 4]);
    float r[8];
    r[0] = fmaxf(dv * (acc[0] + s0.x) + ba.x, 0.0f);
    r[1] = fmaxf(dv * (acc[1] + s0.y) + ba.y, 0.0f);
    r[2] = fmaxf(dv * (acc[2] + s1.x) + ba.z, 0.0f);
    r[3] = fmaxf(dv * (acc[3] + s1.y) + ba.w, 0.0f);
    r[4] = fmaxf(dv * (acc[4] + s2.x) + bb.x, 0.0f);
    r[5] = fmaxf(dv * (acc[5] + s2.y) + bb.y, 0.0f);
    r[6] = fmaxf(dv * (acc[6] + s3.x) + bb.z, 0.0f);
    r[7] = fmaxf(dv * (acc[7] + s3.y) + bb.w, 0.0f);
    __half2 h0 = __floats2half2_rn(r[0], r[1]);
    __half2 h1 = __floats2half2_rn(r[2], r[3]);
    __half2 h2 = __floats2half2_rn(r[4], r[5]);
    __half2 h3 = __floats2half2_rn(r[6], r[7]);
    uint4 o;
    o.x = *reinterpret_cast<uint32_t*>(&h0);
    o.y = *reinterpret_cast<uint32_t*>(&h1);
    o.z = *reinterpret_cast<uint32_t*>(&h2);
    o.w = *reinterpret_cast<uint32_t*>(&h3);
    *reinterpret_cast<uint4*>(&g_hrh[(size_t)g * NH + hl * 8]) = o;
}

// ---------------- pull layer 2 + bias + log_softmax (fp16 gather) ----------
__global__ void k_pull2(const float* __restrict__ b2, float* __restrict__ out) {
    int gw   = (blockIdx.x * blockDim.x + threadIdx.x) >> 5;
    int lane = threadIdx.x & 31;
    if (gw >= NN) return;

    int rs = g_rowptr[gw], re = g_rowptr[gw + 1];
    bool act = (lane < GS / 2);
    float2 acc = make_float2(0.f, 0.f);

    for (int base = rs; base < re; base += 32) {
        int cnt = re - base; if (cnt > 32) cnt = 32;
        int s = 0; float wv = 0.0f;
        if (lane < cnt) {
            uint2 e = g_edge[base + lane];
            s = (int)e.x; wv = __uint_as_float(e.y);
        }
        for (int j = 0; j < cnt; j++) {
            int   sj = __shfl_sync(0xffffffffu, s,  j);
            float wj = __shfl_sync(0xffffffffu, wv, j);
            if (act) {
                uint32_t p = *reinterpret_cast<const uint32_t*>(
                    &g_gsh[(size_t)sj * GS + 2 * lane]);
                float2 f = __half22float2(*reinterpret_cast<__half2*>(&p));
                acc.x += wj * f.x; acc.y += wj * f.y;
            }
        }
    }

    float dv = dinv_of(gw);
    int f0 = 2 * lane, f1 = 2 * lane + 1;
    float v0 = -1e30f, v1 = -1e30f;
    if (act) {
        uint32_t sp = *reinterpret_cast<const uint32_t*>(
            &g_gsh[(size_t)gw * GS + 2 * lane]);
        float2 sf = __half22float2(*reinterpret_cast<__half2*>(&sp));
        if (f0 < NC) v0 = dv * (acc.x + sf.x) + b2[f0];
        if (f1 < NC) v1 = dv * (acc.y + sf.y) + b2[f1];
    }

    float m = fmaxf(v0, v1);
#pragma unroll
    for (int off = 16; off > 0; off >>= 1)
        m = fmaxf(m, __shfl_xor_sync(0xffffffffu, m, off));

    float s = ((f0 < NC && act) ? expf(v0 - m) : 0.0f)
            + ((f1 < NC && act) ? expf(v1 - m) : 0.0f);
#pragma unroll
    for (int off = 16; off > 0; off >>= 1)
        s += __shfl_xor_sync(0xffffffffu, s, off);

    float lse = logf(s) + m;
    if (act && f0 < NC) out[(size_t)gw * NC + f0] = v0 - lse;
    if (act && f1 < NC) out[(size_t)gw * NC + f1] = v1 - lse;
}

// ---------------- launch ---------------------------------------------------
// R14 schedule (measured best): single memset + hist on main; scan/csr chain
// forked to side stream under GEMM1; serial pull1 -> gemm2 -> pull2 tail.
extern "C" void kernel_launch(void* const* d_in, const int* in_sizes, int n_in,
                              void* d_out, int out_size) {
    const float* x  = (const float*)d_in[0];
    const int*   ei = (const int*)  d_in[1];
    const float* ew = (const float*)d_in[2];
    const float* W1 = (const float*)d_in[3];
    const float* b1 = (const float*)d_in[4];
    const float* W2 = (const float*)d_in[5];
    const float* b2 = (const float*)d_in[6];
    float* out = (float*)d_out;

    const int SM1 = 66560;   // GEMM1: BK=32
    const int SM2 = 25088;   // GEMM2: BK=16

    static cudaStream_t s_side = nullptr;
    static cudaEvent_t  s_fork = nullptr, s_join = nullptr;
    static void* p_pk = nullptr;
    if (s_side == nullptr) {
        cudaFuncSetAttribute(k_gemm_p<128, 128, 32, 16, 4, NF, NH, NH, 0>,
                             cudaFuncAttributeMaxDynamicSharedMemorySize, SM1);
        cudaStreamCreateWithFlags(&s_side, cudaStreamNonBlocking);
        cudaEventCreateWithFlags(&s_fork, cudaEventDisableTiming);
        cudaEventCreateWithFlags(&s_join, cudaEventDisableTiming);
        cudaGetSymbolAddress(&p_pk, g_pk);
    }

    cudaMemsetAsync(p_pk, 0, NN * sizeof(unsigned long long), 0);
    k_hist<<<(NE + 255) / 256, 256>>>(ei, ew);

    // fork: side stream builds the CSR while main stream runs GEMM1
    cudaEventRecord(s_fork, 0);
    cudaStreamWaitEvent(s_side, s_fork, 0);
    k_scan1<<<NSB, 256, 0, s_side>>>();
    k_scan2<<<1, 128, 0, s_side>>>();
    k_scan3<<<NSB, 256, 0, s_side>>>();
    k_csr<<<(NE + 255) / 256, 256, 0, s_side>>>(ei, ew);
    cudaEventRecord(s_join, s_side);

    // layer 1 GEMM: hsh = fp16(dinv * (x @ W1))
    k_gemm_p<128, 128, 32, 16, 4, NF, NH, NH, 0>
        <<<(NN + 127) / 128, 256, SM1>>>(x, W1);

    // join: pull1 needs both the CSR (side) and hsh (main)
    cudaStreamWaitEvent(0, s_join, 0);
    k_pull1<<<(NN * 16 + 255) / 256, 256>>>(b1);

    // layer 2: gsh = fp16(dinv * (hrh @ W2))
    k_gemm_p<128, 64, 16, 16, 4, NH, NC, GS, 1>
        <<<(NN + 127) / 128, 128, SM2>>>(nullptr, W2);
    k_pull2<<<(NN * 32 + 255) / 256, 256>>>(b2, out);
}